// round 11
// baseline (speedup 1.0000x reference)
#include <cuda_runtime.h>
#include <stdint.h>

#define IMH 1024
#define IMW 1024
#define NB  8
#define WPR 32   // 32-bit words per image row

// Bit-packed strong/weak planes (static device scratch, no allocs)
__device__ uint32_t g_strong[NB * IMH * WPR];
__device__ uint32_t g_weak[NB * IMH * WPR];

#define ROWS1 64   // output rows per canny_front block

// ---------------------------------------------------------------------------
// K1: round-4 structure verbatim (best measured K1), ROWS1=64.
// Rolling pipeline over full 1024-wide rows, 512 threads x 2 cols each.
// Depth-4 smem row rings carry raw/blurred/magnitude rows; reads always hit
// rows stored >=1 iteration earlier (high ILP, latency-tolerant).
// Pipeline at iter r: store raw(r), bl(r-2), mag(r-4); sync;
// compute bl(r-1), mag+bin(r-3), NMS+threshold+pack row(r-5).
// ---------------------------------------------------------------------------
__global__ void __launch_bounds__(512) canny_front(const float* __restrict__ in,
                                                   int b0)
{
    __shared__ float s_raw[4][1026];
    __shared__ float s_bl [4][1026];
    __shared__ float s_mag[4][1026];

    const int tid = threadIdx.x;              // 0..511
    const int b   = blockIdx.y + b0;
    const int y0  = blockIdx.x * ROWS1;
    const float* img = in + (size_t)b * IMH * IMW;
    const int cx = tid * 2;                   // columns cx, cx+1

    // zero guard columns (index 0 and 1025)
    if (tid < 8) {
        int s = tid & 3, g = (tid >> 2) * 1025;
        s_raw[s][g] = 0.f; s_bl[s][g] = 0.f; s_mag[s][g] = 0.f;
    }

    float blpx = 0.f, blpy = 0.f;    // bl(r-2) pending store
    float magpx = 0.f, magpy = 0.f;  // mag(r-4) pending store
    int bin_m1x = 0, bin_m1y = 0, bin_m2x = 0, bin_m2y = 0;

    const int r_start = y0 - 3, r_end = y0 + ROWS1 + 4;

    float2 rv = make_float2(0.f, 0.f);
    if ((unsigned)r_start < IMH)
        rv = ((const float2*)(img + (size_t)r_start * IMW))[tid];

    for (int r = r_start; r <= r_end; ++r) {
        // ---- store phase ----
        {
            float* pr = s_raw[r & 3];
            float* pb = s_bl[(r - 2) & 3];
            float* pm = s_mag[(r - 4) & 3];
            pr[1 + cx] = rv.x;  pr[2 + cx] = rv.y;
            pb[1 + cx] = blpx;  pb[2 + cx] = blpy;
            pm[1 + cx] = magpx; pm[2 + cx] = magpy;
        }
        __syncthreads();

        // prefetch raw(r+1)
        float2 rvn = make_float2(0.f, 0.f);
        if ((unsigned)(r + 1) < IMH)
            rvn = ((const float2*)(img + (size_t)(r + 1) * IMW))[tid];

        // ---- blur(r-1): direct 9-tap (verbatim expression) ----
        float blnx = 0.f, blny = 0.f;
        if (r >= y0 - 1 && (unsigned)(r - 1) < IMH) {
            const float* t = s_raw[(r - 2) & 3];
            const float* m = s_raw[(r - 1) & 3];
            const float* d = s_raw[r & 3];
            float t0 = t[cx], t1 = t[cx+1], t2 = t[cx+2], t3 = t[cx+3];
            float m0 = m[cx], m1 = m[cx+1], m2 = m[cx+2], m3 = m[cx+3];
            float d0 = d[cx], d1 = d[cx+1], d2 = d[cx+2], d3 = d[cx+3];
            blnx = 0.0625f * t0 + 0.125f * t1 + 0.0625f * t2
                 + 0.125f  * m0 + 0.25f  * m1 + 0.125f  * m2
                 + 0.0625f * d0 + 0.125f * d1 + 0.0625f * d2;
            blny = 0.0625f * t1 + 0.125f * t2 + 0.0625f * t3
                 + 0.125f  * m1 + 0.25f  * m2 + 0.125f  * m3
                 + 0.0625f * d1 + 0.125f * d2 + 0.0625f * d3;
        }

        // ---- sobel + mag + bin at row r-3 (verbatim expressions) ----
        float magnx = 0.f, magny = 0.f; int binnx = 0, binny = 0;
        if (r >= y0 + 2 && (unsigned)(r - 3) < IMH) {
            const float* u = s_bl[(r - 4) & 3];
            const float* c = s_bl[(r - 3) & 3];
            const float* d = s_bl[(r - 2) & 3];
            float u0 = u[cx], u1 = u[cx+1], u2 = u[cx+2], u3 = u[cx+3];
            float c0 = c[cx], c1 = c[cx+1], c2 = c[cx+2], c3 = c[cx+3];
            float d0 = d[cx], d1 = d[cx+1], d2 = d[cx+2], d3 = d[cx+3];
            {
                float gx = (u2 - u0) + 2.0f * (c2 - c0) + (d2 - d0);
                float gy = (d0 - u0) + 2.0f * (d1 - u1) + (d2 - u2);
                magnx = sqrtf(gx * gx + gy * gy);
                float ax = fabsf(gx), ay = fabsf(gy);
                bool ss = ((__float_as_uint(gx) ^ __float_as_uint(gy)) >> 31) == 0u;
                binnx = (ay < 0.41421356237309503f * ax) ? 0 :
                        (ay >= 2.414213562373095f  * ax) ? 2 : (ss ? 1 : 3);
            }
            {
                float gx = (u3 - u1) + 2.0f * (c3 - c1) + (d3 - d1);
                float gy = (d1 - u1) + 2.0f * (d2 - u2) + (d3 - u3);
                magny = sqrtf(gx * gx + gy * gy);
                float ax = fabsf(gx), ay = fabsf(gy);
                bool ss = ((__float_as_uint(gx) ^ __float_as_uint(gy)) >> 31) == 0u;
                binny = (ay < 0.41421356237309503f * ax) ? 0 :
                        (ay >= 2.414213562373095f  * ax) ? 2 : (ss ? 1 : 3);
            }
        }

        // ---- NMS + double threshold + bitpack at row r-5 ----
        if (r >= y0 + 5) {
            const float* mU = s_mag[(r - 6) & 3];
            const float* mC = s_mag[(r - 5) & 3];
            const float* mD = s_mag[(r - 4) & 3];
            bool s0, w0, s1, w1;
            {
                float m = mC[1 + cx];
                int bin = bin_m2x;
                int dc = (bin <= 1) ? 1 : ((bin == 2) ? 0 : -1);
                const float* p1 = (bin == 0) ? mC : mU;
                const float* p2 = (bin == 0) ? mC : mD;
                float n1 = p1[1 + cx + dc], n2 = p2[1 + cx - dc];
                float sup = (m >= n1 && m >= n2) ? m : 0.f;
                s0 = sup >= 0.3f;
                w0 = (sup >= 0.1f) && (sup < 0.3f);
            }
            {
                float m = mC[2 + cx];
                int bin = bin_m2y;
                int dc = (bin <= 1) ? 1 : ((bin == 2) ? 0 : -1);
                const float* p1 = (bin == 0) ? mC : mU;
                const float* p2 = (bin == 0) ? mC : mD;
                float n1 = p1[2 + cx + dc], n2 = p2[2 + cx - dc];
                float sup = (m >= n1 && m >= n2) ? m : 0.f;
                s1 = sup >= 0.3f;
                w1 = (sup >= 0.1f) && (sup < 0.3f);
            }
            unsigned vs = (s0 ? 1u : 0u) | (s1 ? 2u : 0u);
            unsigned vw = (w0 ? 1u : 0u) | (w1 ? 2u : 0u);
            unsigned mask = ((tid >> 4) & 1) ? 0xFFFF0000u : 0x0000FFFFu;
            int sh = 2 * (tid & 15);
            unsigned ws = __reduce_or_sync(mask, vs << sh);
            unsigned ww = __reduce_or_sync(mask, vw << sh);
            if ((tid & 15) == 0) {
                int idx = (b * IMH + (r - 5)) * WPR + (cx >> 5);
                g_strong[idx] = ws;
                g_weak[idx]   = ww;
            }
        }

        // ---- ring shifts ----
        blpx = blnx; blpy = blny;
        magpx = magnx; magpy = magny;
        bin_m2x = bin_m1x; bin_m2y = bin_m1y; bin_m1x = binnx; bin_m1y = binny;
        rv = rvn;
    }
}

// ---------------------------------------------------------------------------
// K2: 16 hysteresis iterations, rows in registers (8/warp), horizontal word
// neighbors via shuffles, vertical strip-boundary rows via tiny double-
// buffered smem exchange. One barrier per iteration. Tile = 64 data rows
// (16 halo + 32 interior + 16 halo), full 1024 width; grid 32x(NB/2).
// Stale-halo front advances 1 row/iter -> interior exact after 16 iters.
// ---------------------------------------------------------------------------
__global__ void __launch_bounds__(256) canny_hyst(float* __restrict__ out,
                                                  int b0)
{
    __shared__ uint32_t sm_top[2][8][32];
    __shared__ uint32_t sm_bot[2][8][32];
    __shared__ uint32_t Efin[32][32];

    const int tid  = threadIdx.x;
    const int lane = tid & 31;           // word column
    const int w    = tid >> 5;           // warp id 0..7 -> data rows 8w..8w+7
    const int by   = blockIdx.x;         // 0..31
    const int b    = blockIdx.y + b0;
    const int r0   = by * 32;

    uint32_t e[8], wk[8];
    #pragma unroll
    for (int k = 0; k < 8; k++) {
        int gr = r0 - 16 + 8 * w + k;
        uint32_t ev = 0u, wv = 0u;
        if ((unsigned)gr < IMH) {
            int idx = (b * IMH + gr) * WPR + lane;
            ev = g_strong[idx];
            wv = g_weak[idx];
        }
        e[k] = ev; wk[k] = wv;
    }

    for (int it = 0; it < 16; ++it) {
        const int p = it & 1;
        sm_top[p][w][lane] = e[0];
        sm_bot[p][w][lane] = e[7];
        __syncthreads();
        uint32_t above = (w > 0) ? sm_bot[p][w - 1][lane] : 0u;
        uint32_t below = (w < 7) ? sm_top[p][w + 1][lane] : 0u;

        uint32_t rowv[10];
        rowv[0] = above;
        #pragma unroll
        for (int k = 0; k < 8; k++) rowv[k + 1] = e[k];
        rowv[9] = below;

        uint32_t h[10];
        #pragma unroll
        for (int k = 0; k < 10; k++) {
            uint32_t m = rowv[k];
            uint32_t l  = __shfl_up_sync(0xffffffffu, m, 1);
            uint32_t rr = __shfl_down_sync(0xffffffffu, m, 1);
            if (lane == 0)  l = 0u;
            if (lane == 31) rr = 0u;
            h[k] = m | (m << 1) | (m >> 1) | (l >> 31) | (rr << 31);
        }
        #pragma unroll
        for (int k = 0; k < 8; k++)
            e[k] = e[k] | (wk[k] & (h[k] | h[k + 1] | h[k + 2]));
    }

    // publish interior rows (data rows 16..47 -> global rows r0..r0+31)
    #pragma unroll
    for (int k = 0; k < 8; k++) {
        int dr = 8 * w + k;
        if (dr >= 16 && dr < 48) Efin[dr - 16][lane] = e[k];
    }
    __syncthreads();

    float4* o = (float4*)(out + (size_t)b * IMH * IMW + (size_t)r0 * IMW);
    #pragma unroll
    for (int u = tid; u < 32 * 256; u += 256) {
        int row = u >> 8;                 // 256 float4 per image row
        int q   = u & 255;
        int colpx = q << 2;
        uint32_t word = Efin[row][colpx >> 5];
        int sh = colpx & 31;
        float4 v;
        v.x = (float)((word >> sh)       & 1u);
        v.y = (float)((word >> (sh + 1)) & 1u);
        v.z = (float)((word >> (sh + 2)) & 1u);
        v.w = (float)((word >> (sh + 3)) & 1u);
        o[(row << 8) + q] = v;
    }
}

extern "C" void kernel_launch(void* const* d_in, const int* in_sizes, int n_in,
                              void* d_out, int out_size)
{
    const float* in = (const float*)d_in[0];
    float* out = (float*)d_out;

    // Split each stage into two half-image launches: identical total work,
    // and the 4-launch replay period lets ncu (-s 5 -c 1) land on canny_front.
    dim3 g1(IMH / ROWS1, NB / 2);     // 16 x 4
    canny_front<<<g1, 512>>>(in, 0);
    canny_front<<<g1, 512>>>(in, 4);

    dim3 g2(32, NB / 2);              // 32 x 4
    canny_hyst<<<g2, 256>>>(out, 0);
    canny_hyst<<<g2, 256>>>(out, 4);
}

// round 12
// speedup vs baseline: 2.0578x; 2.0578x over previous
#include <cuda_runtime.h>
#include <stdint.h>

#define IMH 1024
#define IMW 1024
#define NB  8
#define WPR 32   // 32-bit words per image row

// Bit-packed strong/weak planes (static device scratch, no allocs)
__device__ uint32_t g_strong[NB * IMH * WPR];
__device__ uint32_t g_weak[NB * IMH * WPR];

#define ROWS1 16   // output rows per canny_front block -> 512 blocks, ~3/SM

// ---------------------------------------------------------------------------
// K1: round-4 structure verbatim (best measured K1), ROWS1=16 for maximum
// block-level co-residency (latency/barrier-bound kernel: co-resident blocks
// interleave and hide each other's barrier+LDS latency).
// Rolling pipeline over full 1024-wide rows, 512 threads x 2 cols each.
// Depth-4 smem row rings carry raw/blurred/magnitude rows; reads always hit
// rows stored >=1 iteration earlier (high ILP, latency-tolerant).
// Pipeline at iter r: store raw(r), bl(r-2), mag(r-4); sync;
// compute bl(r-1), mag+bin(r-3), NMS+threshold+pack row(r-5).
// ---------------------------------------------------------------------------
__global__ void __launch_bounds__(512) canny_front(const float* __restrict__ in)
{
    __shared__ float s_raw[4][1026];
    __shared__ float s_bl [4][1026];
    __shared__ float s_mag[4][1026];

    const int tid = threadIdx.x;              // 0..511
    const int b   = blockIdx.y;
    const int y0  = blockIdx.x * ROWS1;
    const float* img = in + (size_t)b * IMH * IMW;
    const int cx = tid * 2;                   // columns cx, cx+1

    // zero guard columns (index 0 and 1025)
    if (tid < 8) {
        int s = tid & 3, g = (tid >> 2) * 1025;
        s_raw[s][g] = 0.f; s_bl[s][g] = 0.f; s_mag[s][g] = 0.f;
    }

    float blpx = 0.f, blpy = 0.f;    // bl(r-2) pending store
    float magpx = 0.f, magpy = 0.f;  // mag(r-4) pending store
    int bin_m1x = 0, bin_m1y = 0, bin_m2x = 0, bin_m2y = 0;

    const int r_start = y0 - 3, r_end = y0 + ROWS1 + 4;

    float2 rv = make_float2(0.f, 0.f);
    if ((unsigned)r_start < IMH)
        rv = ((const float2*)(img + (size_t)r_start * IMW))[tid];

    for (int r = r_start; r <= r_end; ++r) {
        // ---- store phase ----
        {
            float* pr = s_raw[r & 3];
            float* pb = s_bl[(r - 2) & 3];
            float* pm = s_mag[(r - 4) & 3];
            pr[1 + cx] = rv.x;  pr[2 + cx] = rv.y;
            pb[1 + cx] = blpx;  pb[2 + cx] = blpy;
            pm[1 + cx] = magpx; pm[2 + cx] = magpy;
        }
        __syncthreads();

        // prefetch raw(r+1)
        float2 rvn = make_float2(0.f, 0.f);
        if ((unsigned)(r + 1) < IMH)
            rvn = ((const float2*)(img + (size_t)(r + 1) * IMW))[tid];

        // ---- blur(r-1): direct 9-tap (verbatim expression) ----
        float blnx = 0.f, blny = 0.f;
        if (r >= y0 - 1 && (unsigned)(r - 1) < IMH) {
            const float* t = s_raw[(r - 2) & 3];
            const float* m = s_raw[(r - 1) & 3];
            const float* d = s_raw[r & 3];
            float t0 = t[cx], t1 = t[cx+1], t2 = t[cx+2], t3 = t[cx+3];
            float m0 = m[cx], m1 = m[cx+1], m2 = m[cx+2], m3 = m[cx+3];
            float d0 = d[cx], d1 = d[cx+1], d2 = d[cx+2], d3 = d[cx+3];
            blnx = 0.0625f * t0 + 0.125f * t1 + 0.0625f * t2
                 + 0.125f  * m0 + 0.25f  * m1 + 0.125f  * m2
                 + 0.0625f * d0 + 0.125f * d1 + 0.0625f * d2;
            blny = 0.0625f * t1 + 0.125f * t2 + 0.0625f * t3
                 + 0.125f  * m1 + 0.25f  * m2 + 0.125f  * m3
                 + 0.0625f * d1 + 0.125f * d2 + 0.0625f * d3;
        }

        // ---- sobel + mag + bin at row r-3 (verbatim expressions) ----
        float magnx = 0.f, magny = 0.f; int binnx = 0, binny = 0;
        if (r >= y0 + 2 && (unsigned)(r - 3) < IMH) {
            const float* u = s_bl[(r - 4) & 3];
            const float* c = s_bl[(r - 3) & 3];
            const float* d = s_bl[(r - 2) & 3];
            float u0 = u[cx], u1 = u[cx+1], u2 = u[cx+2], u3 = u[cx+3];
            float c0 = c[cx], c1 = c[cx+1], c2 = c[cx+2], c3 = c[cx+3];
            float d0 = d[cx], d1 = d[cx+1], d2 = d[cx+2], d3 = d[cx+3];
            {
                float gx = (u2 - u0) + 2.0f * (c2 - c0) + (d2 - d0);
                float gy = (d0 - u0) + 2.0f * (d1 - u1) + (d2 - u2);
                magnx = sqrtf(gx * gx + gy * gy);
                float ax = fabsf(gx), ay = fabsf(gy);
                bool ss = ((__float_as_uint(gx) ^ __float_as_uint(gy)) >> 31) == 0u;
                binnx = (ay < 0.41421356237309503f * ax) ? 0 :
                        (ay >= 2.414213562373095f  * ax) ? 2 : (ss ? 1 : 3);
            }
            {
                float gx = (u3 - u1) + 2.0f * (c3 - c1) + (d3 - d1);
                float gy = (d1 - u1) + 2.0f * (d2 - u2) + (d3 - u3);
                magny = sqrtf(gx * gx + gy * gy);
                float ax = fabsf(gx), ay = fabsf(gy);
                bool ss = ((__float_as_uint(gx) ^ __float_as_uint(gy)) >> 31) == 0u;
                binny = (ay < 0.41421356237309503f * ax) ? 0 :
                        (ay >= 2.414213562373095f  * ax) ? 2 : (ss ? 1 : 3);
            }
        }

        // ---- NMS + double threshold + bitpack at row r-5 ----
        if (r >= y0 + 5) {
            const float* mU = s_mag[(r - 6) & 3];
            const float* mC = s_mag[(r - 5) & 3];
            const float* mD = s_mag[(r - 4) & 3];
            bool s0, w0, s1, w1;
            {
                float m = mC[1 + cx];
                int bin = bin_m2x;
                int dc = (bin <= 1) ? 1 : ((bin == 2) ? 0 : -1);
                const float* p1 = (bin == 0) ? mC : mU;
                const float* p2 = (bin == 0) ? mC : mD;
                float n1 = p1[1 + cx + dc], n2 = p2[1 + cx - dc];
                float sup = (m >= n1 && m >= n2) ? m : 0.f;
                s0 = sup >= 0.3f;
                w0 = (sup >= 0.1f) && (sup < 0.3f);
            }
            {
                float m = mC[2 + cx];
                int bin = bin_m2y;
                int dc = (bin <= 1) ? 1 : ((bin == 2) ? 0 : -1);
                const float* p1 = (bin == 0) ? mC : mU;
                const float* p2 = (bin == 0) ? mC : mD;
                float n1 = p1[2 + cx + dc], n2 = p2[2 + cx - dc];
                float sup = (m >= n1 && m >= n2) ? m : 0.f;
                s1 = sup >= 0.3f;
                w1 = (sup >= 0.1f) && (sup < 0.3f);
            }
            unsigned vs = (s0 ? 1u : 0u) | (s1 ? 2u : 0u);
            unsigned vw = (w0 ? 1u : 0u) | (w1 ? 2u : 0u);
            unsigned mask = ((tid >> 4) & 1) ? 0xFFFF0000u : 0x0000FFFFu;
            int sh = 2 * (tid & 15);
            unsigned ws = __reduce_or_sync(mask, vs << sh);
            unsigned ww = __reduce_or_sync(mask, vw << sh);
            if ((tid & 15) == 0) {
                int idx = (b * IMH + (r - 5)) * WPR + (cx >> 5);
                g_strong[idx] = ws;
                g_weak[idx]   = ww;
            }
        }

        // ---- ring shifts ----
        blpx = blnx; blpy = blny;
        magpx = magnx; magpy = magny;
        bin_m2x = bin_m1x; bin_m2y = bin_m1y; bin_m1x = binnx; bin_m1y = binny;
        rv = rvn;
    }
}

// ---------------------------------------------------------------------------
// K2: 16 hysteresis iterations, rows in registers (8/warp), horizontal word
// neighbors via shuffles, vertical strip-boundary rows via tiny double-
// buffered smem exchange. One barrier per iteration. Tile = 64 data rows
// (16 halo + 32 interior + 16 halo), full 1024 width; grid 32x8 = 256 blocks.
// Stale-halo front advances 1 row/iter -> interior exact after 16 iters.
// ---------------------------------------------------------------------------
__global__ void __launch_bounds__(256) canny_hyst(float* __restrict__ out)
{
    __shared__ uint32_t sm_top[2][8][32];
    __shared__ uint32_t sm_bot[2][8][32];
    __shared__ uint32_t Efin[32][32];

    const int tid  = threadIdx.x;
    const int lane = tid & 31;           // word column
    const int w    = tid >> 5;           // warp id 0..7 -> data rows 8w..8w+7
    const int by   = blockIdx.x;         // 0..31
    const int b    = blockIdx.y;
    const int r0   = by * 32;

    uint32_t e[8], wk[8];
    #pragma unroll
    for (int k = 0; k < 8; k++) {
        int gr = r0 - 16 + 8 * w + k;
        uint32_t ev = 0u, wv = 0u;
        if ((unsigned)gr < IMH) {
            int idx = (b * IMH + gr) * WPR + lane;
            ev = g_strong[idx];
            wv = g_weak[idx];
        }
        e[k] = ev; wk[k] = wv;
    }

    for (int it = 0; it < 16; ++it) {
        const int p = it & 1;
        sm_top[p][w][lane] = e[0];
        sm_bot[p][w][lane] = e[7];
        __syncthreads();
        uint32_t above = (w > 0) ? sm_bot[p][w - 1][lane] : 0u;
        uint32_t below = (w < 7) ? sm_top[p][w + 1][lane] : 0u;

        uint32_t rowv[10];
        rowv[0] = above;
        #pragma unroll
        for (int k = 0; k < 8; k++) rowv[k + 1] = e[k];
        rowv[9] = below;

        uint32_t h[10];
        #pragma unroll
        for (int k = 0; k < 10; k++) {
            uint32_t m = rowv[k];
            uint32_t l  = __shfl_up_sync(0xffffffffu, m, 1);
            uint32_t rr = __shfl_down_sync(0xffffffffu, m, 1);
            if (lane == 0)  l = 0u;
            if (lane == 31) rr = 0u;
            h[k] = m | (m << 1) | (m >> 1) | (l >> 31) | (rr << 31);
        }
        #pragma unroll
        for (int k = 0; k < 8; k++)
            e[k] = e[k] | (wk[k] & (h[k] | h[k + 1] | h[k + 2]));
    }

    // publish interior rows (data rows 16..47 -> global rows r0..r0+31)
    #pragma unroll
    for (int k = 0; k < 8; k++) {
        int dr = 8 * w + k;
        if (dr >= 16 && dr < 48) Efin[dr - 16][lane] = e[k];
    }
    __syncthreads();

    float4* o = (float4*)(out + (size_t)b * IMH * IMW + (size_t)r0 * IMW);
    #pragma unroll
    for (int u = tid; u < 32 * 256; u += 256) {
        int row = u >> 8;                 // 256 float4 per image row
        int q   = u & 255;
        int colpx = q << 2;
        uint32_t word = Efin[row][colpx >> 5];
        int sh = colpx & 31;
        float4 v;
        v.x = (float)((word >> sh)       & 1u);
        v.y = (float)((word >> (sh + 1)) & 1u);
        v.z = (float)((word >> (sh + 2)) & 1u);
        v.w = (float)((word >> (sh + 3)) & 1u);
        o[(row << 8) + q] = v;
    }
}

extern "C" void kernel_launch(void* const* d_in, const int* in_sizes, int n_in,
                              void* d_out, int out_size)
{
    const float* in = (const float*)d_in[0];
    float* out = (float*)d_out;

    dim3 g1(IMH / ROWS1, NB);     // 64 x 8 = 512 blocks
    canny_front<<<g1, 512>>>(in);

    dim3 g2(32, NB);              // 32 x 8 = 256 blocks
    canny_hyst<<<g2, 256>>>(out);
}

// round 13
// speedup vs baseline: 2.2431x; 1.0900x over previous
#include <cuda_runtime.h>
#include <stdint.h>

#define IMH 1024
#define IMW 1024
#define NB  8
#define WPR 32   // 32-bit words per image row

// Bit-packed strong/weak planes (static device scratch, no allocs)
__device__ uint32_t g_strong[NB * IMH * WPR];
__device__ uint32_t g_weak[NB * IMH * WPR];

#define ROWS1 32   // output rows per canny_front block

// ---- verbatim round-4 math, parameterized by row pointers ----
#define BLUR9(A,B,C,out) do { \
    float t0=(A)[cx],t1=(A)[cx+1],t2=(A)[cx+2],t3=(A)[cx+3]; \
    float m0=(B)[cx],m1=(B)[cx+1],m2=(B)[cx+2],m3=(B)[cx+3]; \
    float d0=(C)[cx],d1=(C)[cx+1],d2=(C)[cx+2],d3=(C)[cx+3]; \
    (out).x = 0.0625f * t0 + 0.125f * t1 + 0.0625f * t2 \
            + 0.125f  * m0 + 0.25f  * m1 + 0.125f  * m2 \
            + 0.0625f * d0 + 0.125f * d1 + 0.0625f * d2; \
    (out).y = 0.0625f * t1 + 0.125f * t2 + 0.0625f * t3 \
            + 0.125f  * m1 + 0.25f  * m2 + 0.125f  * m3 \
            + 0.0625f * d1 + 0.125f * d2 + 0.0625f * d3; \
} while(0)

#define SOBEL(U,C,D,magv,binx,biny) do { \
    float u0=(U)[cx],u1=(U)[cx+1],u2=(U)[cx+2],u3=(U)[cx+3]; \
    float c0=(C)[cx],c1=(C)[cx+1],c2=(C)[cx+2],c3=(C)[cx+3]; \
    float d0=(D)[cx],d1=(D)[cx+1],d2=(D)[cx+2],d3=(D)[cx+3]; \
    { float gx = (u2 - u0) + 2.0f * (c2 - c0) + (d2 - d0); \
      float gy = (d0 - u0) + 2.0f * (d1 - u1) + (d2 - u2); \
      (magv).x = sqrtf(gx * gx + gy * gy); \
      float ax = fabsf(gx), ay = fabsf(gy); \
      bool ss = ((__float_as_uint(gx) ^ __float_as_uint(gy)) >> 31) == 0u; \
      binx = (ay < 0.41421356237309503f * ax) ? 0 : \
             (ay >= 2.414213562373095f  * ax) ? 2 : (ss ? 1 : 3); } \
    { float gx = (u3 - u1) + 2.0f * (c3 - c1) + (d3 - d1); \
      float gy = (d1 - u1) + 2.0f * (d2 - u2) + (d3 - u3); \
      (magv).y = sqrtf(gx * gx + gy * gy); \
      float ax = fabsf(gx), ay = fabsf(gy); \
      bool ss = ((__float_as_uint(gx) ^ __float_as_uint(gy)) >> 31) == 0u; \
      biny = (ay < 0.41421356237309503f * ax) ? 0 : \
             (ay >= 2.414213562373095f  * ax) ? 2 : (ss ? 1 : 3); } \
} while(0)

#define NMSPACK(MU,MC,MD,BINX,BINY,ROWN) do { \
    bool s0,w0,s1,w1; \
    { float m = (MC)[1+cx]; int bin = (BINX); \
      int dc = (bin <= 1) ? 1 : ((bin == 2) ? 0 : -1); \
      const float* p1 = (bin == 0) ? (MC) : (MU); \
      const float* p2 = (bin == 0) ? (MC) : (MD); \
      float n1 = p1[1 + cx + dc], n2 = p2[1 + cx - dc]; \
      float sup = (m >= n1 && m >= n2) ? m : 0.f; \
      s0 = sup >= 0.3f; w0 = (sup >= 0.1f) && (sup < 0.3f); } \
    { float m = (MC)[2+cx]; int bin = (BINY); \
      int dc = (bin <= 1) ? 1 : ((bin == 2) ? 0 : -1); \
      const float* p1 = (bin == 0) ? (MC) : (MU); \
      const float* p2 = (bin == 0) ? (MC) : (MD); \
      float n1 = p1[2 + cx + dc], n2 = p2[2 + cx - dc]; \
      float sup = (m >= n1 && m >= n2) ? m : 0.f; \
      s1 = sup >= 0.3f; w1 = (sup >= 0.1f) && (sup < 0.3f); } \
    unsigned vs = (s0 ? 1u : 0u) | (s1 ? 2u : 0u); \
    unsigned vw = (w0 ? 1u : 0u) | (w1 ? 2u : 0u); \
    unsigned msk = ((tid >> 4) & 1) ? 0xFFFF0000u : 0x0000FFFFu; \
    int sh = 2 * (tid & 15); \
    unsigned ws = __reduce_or_sync(msk, vs << sh); \
    unsigned ww = __reduce_or_sync(msk, vw << sh); \
    if ((tid & 15) == 0) { \
        int idx = (b * IMH + (ROWN)) * WPR + (cx >> 5); \
        g_strong[idx] = ws; g_weak[idx] = ww; } \
} while(0)

// One pair-iteration. S = compile-time slot of row r (slot(n) = (n-(y0-3)) mod 6).
// Stores raw(r),raw(r+1), bl(r-3),bl(r-2), mag(r-6),mag(r-5); sync;
// prefetch raw(r+2,r+3); compute bl(r-1,r), mag+bin(r-4,r-3); NMS rows (r-7,r-6).
// Overwrite hazards: each overwritten row's last reader ran 2 pair-iterations
// earlier, separated by an intervening __syncthreads -> depth-6 rings safe.
#define BODY(S) do { \
    { float* pr0 = s_raw[(S+0)%6]; float* pr1 = s_raw[(S+1)%6]; \
      float* pb0 = s_bl [(S+3)%6]; float* pb1 = s_bl [(S+4)%6]; \
      float* pm0 = s_mag[(S+0)%6]; float* pm1 = s_mag[(S+1)%6]; \
      pr0[1+cx]=rv0.x; pr0[2+cx]=rv0.y; pr1[1+cx]=rv1.x; pr1[2+cx]=rv1.y; \
      pb0[1+cx]=blp0.x; pb0[2+cx]=blp0.y; pb1[1+cx]=blp1.x; pb1[2+cx]=blp1.y; \
      pm0[1+cx]=magp0.x; pm0[2+cx]=magp0.y; pm1[1+cx]=magp1.x; pm1[2+cx]=magp1.y; } \
    __syncthreads(); \
    rv0 = make_float2(0.f,0.f); rv1 = make_float2(0.f,0.f); \
    if ((unsigned)(r+2) < IMH) rv0 = ((const float2*)(img + (size_t)(r+2) * IMW))[tid]; \
    if ((unsigned)(r+3) < IMH) rv1 = ((const float2*)(img + (size_t)(r+3) * IMW))[tid]; \
    { const float* q0 = s_raw[(S+4)%6]; const float* q1 = s_raw[(S+5)%6]; \
      const float* q2 = s_raw[(S+0)%6]; const float* q3 = s_raw[(S+1)%6]; \
      float2 bn0 = make_float2(0.f,0.f), bn1 = make_float2(0.f,0.f); \
      if (r >= y0 - 1 && (unsigned)(r-1) < IMH) BLUR9(q0,q1,q2,bn0); \
      if (r >= y0 - 2 && (unsigned)(r)   < IMH) BLUR9(q1,q2,q3,bn1); \
      blp0 = bn0; blp1 = bn1; } \
    { const float* v0 = s_bl[(S+1)%6]; const float* v1 = s_bl[(S+2)%6]; \
      const float* v2 = s_bl[(S+3)%6]; const float* v3 = s_bl[(S+4)%6]; \
      float2 mg0 = make_float2(0.f,0.f), mg1 = make_float2(0.f,0.f); \
      int bAx=0,bAy=0,bBx=0,bBy=0; \
      if (r >= y0 + 3 && (unsigned)(r-4) < IMH) SOBEL(v0,v1,v2,mg0,bAx,bAy); \
      if (r >= y0 + 2 && (unsigned)(r-3) < IMH) SOBEL(v1,v2,v3,mg1,bBx,bBy); \
      { const float* n0 = s_mag[(S+4)%6]; const float* n1 = s_mag[(S+5)%6]; \
        const float* n2 = s_mag[(S+0)%6]; const float* n3 = s_mag[(S+1)%6]; \
        if (r >= y0 + 7 && r < y0 + ROWS1 + 7) NMSPACK(n0,n1,n2,binB2x,binB2y,(r-7)); \
        if (r >= y0 + 6 && r < y0 + ROWS1 + 6) NMSPACK(n1,n2,n3,binA1x,binA1y,(r-6)); } \
      magp0 = mg0; magp1 = mg1; \
      binB2x = binB1x; binB2y = binB1y; \
      binB1x = bBx; binB1y = bBy; binA1x = bAx; binA1y = bAy; } \
    r += 2; \
} while(0)

// ---------------------------------------------------------------------------
// K1: 2-row-paired rolling pipeline, 512 threads x 2 cols, full-width rows.
// Depth-6 smem rings, one barrier per PAIR of rows (21 barriers vs 40).
// Loop unrolled by 3 bodies so ring slots are compile-time constants.
// ---------------------------------------------------------------------------
__global__ void __launch_bounds__(512, 2) canny_front(const float* __restrict__ in)
{
    __shared__ float s_raw[6][1026];
    __shared__ float s_bl [6][1026];
    __shared__ float s_mag[6][1026];

    const int tid = threadIdx.x;              // 0..511
    const int b   = blockIdx.y;
    const int y0  = blockIdx.x * ROWS1;
    const float* img = in + (size_t)b * IMH * IMW;
    const int cx = tid * 2;                   // columns cx, cx+1

    // zero guard columns (index 0 and 1025), all 6 slots
    if (tid < 12) {
        int s = tid % 6, g = (tid / 6) * 1025;
        s_raw[s][g] = 0.f; s_bl[s][g] = 0.f; s_mag[s][g] = 0.f;
    }

    float2 blp0  = make_float2(0.f,0.f), blp1  = make_float2(0.f,0.f);
    float2 magp0 = make_float2(0.f,0.f), magp1 = make_float2(0.f,0.f);
    int binA1x=0, binA1y=0, binB1x=0, binB1y=0, binB2x=0, binB2y=0;

    int r = y0 - 3;
    float2 rv0 = make_float2(0.f,0.f), rv1 = make_float2(0.f,0.f);
    if ((unsigned)r       < IMH) rv0 = ((const float2*)(img + (size_t)r       * IMW))[tid];
    if ((unsigned)(r + 1) < IMH) rv1 = ((const float2*)(img + (size_t)(r + 1) * IMW))[tid];

    // 21 pair-iterations = 7 x (slots 0,2,4)
    #pragma unroll 1
    for (int jj = 0; jj < 7; ++jj) {
        BODY(0);
        BODY(2);
        BODY(4);
    }
}

// ---------------------------------------------------------------------------
// K2: 16 hysteresis iterations, rows in registers (8/warp), horizontal word
// neighbors via shuffles, vertical strip-boundary rows via tiny double-
// buffered smem exchange. One barrier per iteration. Tile = 64 data rows
// (16 halo + 32 interior + 16 halo), full 1024 width; grid 32x8 = 256 blocks.
// Float expansion via 16-entry float4 LUT in smem (1 LDS.128 per 4 pixels).
// ---------------------------------------------------------------------------
__global__ void __launch_bounds__(256) canny_hyst(float* __restrict__ out)
{
    __shared__ uint32_t sm_top[2][8][32];
    __shared__ uint32_t sm_bot[2][8][32];
    __shared__ uint32_t Efin[32][32];
    __shared__ float4   lut4[16];

    const int tid  = threadIdx.x;
    const int lane = tid & 31;           // word column
    const int w    = tid >> 5;           // warp id 0..7 -> data rows 8w..8w+7
    const int by   = blockIdx.x;         // 0..31
    const int b    = blockIdx.y;
    const int r0   = by * 32;

    if (tid < 16) {
        lut4[tid] = make_float4((float)(tid & 1), (float)((tid >> 1) & 1),
                                (float)((tid >> 2) & 1), (float)((tid >> 3) & 1));
    }

    uint32_t e[8], wk[8];
    #pragma unroll
    for (int k = 0; k < 8; k++) {
        int gr = r0 - 16 + 8 * w + k;
        uint32_t ev = 0u, wv = 0u;
        if ((unsigned)gr < IMH) {
            int idx = (b * IMH + gr) * WPR + lane;
            ev = g_strong[idx];
            wv = g_weak[idx];
        }
        e[k] = ev; wk[k] = wv;
    }

    #pragma unroll 2
    for (int it = 0; it < 16; ++it) {
        const int p = it & 1;
        sm_top[p][w][lane] = e[0];
        sm_bot[p][w][lane] = e[7];
        __syncthreads();
        uint32_t above = (w > 0) ? sm_bot[p][w - 1][lane] : 0u;
        uint32_t below = (w < 7) ? sm_top[p][w + 1][lane] : 0u;

        uint32_t rowv[10];
        rowv[0] = above;
        #pragma unroll
        for (int k = 0; k < 8; k++) rowv[k + 1] = e[k];
        rowv[9] = below;

        uint32_t h[10];
        #pragma unroll
        for (int k = 0; k < 10; k++) {
            uint32_t m = rowv[k];
            uint32_t l  = __shfl_up_sync(0xffffffffu, m, 1);
            uint32_t rr = __shfl_down_sync(0xffffffffu, m, 1);
            if (lane == 0)  l = 0u;
            if (lane == 31) rr = 0u;
            h[k] = m | (m << 1) | (m >> 1) | (l >> 31) | (rr << 31);
        }
        #pragma unroll
        for (int k = 0; k < 8; k++)
            e[k] = e[k] | (wk[k] & (h[k] | h[k + 1] | h[k + 2]));
    }

    // publish interior rows (data rows 16..47 -> global rows r0..r0+31)
    #pragma unroll
    for (int k = 0; k < 8; k++) {
        int dr = 8 * w + k;
        if (dr >= 16 && dr < 48) Efin[dr - 16][lane] = e[k];
    }
    __syncthreads();

    float4* o = (float4*)(out + (size_t)b * IMH * IMW + (size_t)r0 * IMW);
    #pragma unroll
    for (int u = tid; u < 32 * 256; u += 256) {
        int row = u >> 8;                 // 256 float4 per image row
        int q   = u & 255;
        int colpx = q << 2;
        uint32_t word = Efin[row][colpx >> 5];
        o[(row << 8) + q] = lut4[(word >> (colpx & 31)) & 15u];
    }
}

extern "C" void kernel_launch(void* const* d_in, const int* in_sizes, int n_in,
                              void* d_out, int out_size)
{
    const float* in = (const float*)d_in[0];
    float* out = (float*)d_out;

    dim3 g1(IMH / ROWS1, NB);     // 32 x 8 = 256 blocks
    canny_front<<<g1, 512>>>(in);

    dim3 g2(32, NB);              // 32 x 8 = 256 blocks
    canny_hyst<<<g2, 256>>>(out);
}